// round 9
// baseline (speedup 1.0000x reference)
#include <cuda_runtime.h>

#define NN 50000
#define EE 800000
#define ET (EE + NN)
#define NEG_SLOPE 0.2f
#define FULLMASK 0xFFFFFFFFu
#define SCAN_B 1024
#define NBLK ((NN + SCAN_B - 1) / SCAN_B)   // 49
#define DEGCAP 128

// -------- scratch (static __device__ — no allocations allowed) --------
__device__ float g_h[NN * 64];
__device__ float g_x2[NN * 64];
__device__ float g_as[NN];
__device__ float g_ad[NN];
__device__ int   g_cnt[NN];
__device__ int   g_off[NN + 1];
__device__ int   g_cur[NN];
__device__ int   g_csr[ET];
__device__ int   g_pub[NBLK];       // decoupled-lookback: (value<<2)|state
__device__ int   g_is64;

// host-side stream/event for graph fork
static cudaStream_t g_s2;
static cudaEvent_t  g_evF, g_evJ;
static struct StreamInit {
    StreamInit() {
        cudaStreamCreateWithFlags(&g_s2, cudaStreamNonBlocking);
        cudaEventCreateWithFlags(&g_evF, cudaEventDisableTiming);
        cudaEventCreateWithFlags(&g_evJ, cudaEventDisableTiming);
    }
} g_stream_init;

// -------- dtype detection --------
__global__ void detect_dtype(const int* __restrict__ ei32) {
    int any = 0;
    for (int i = threadIdx.x; i < 1024; i += 256)
        if (ei32[2 * i + 1] != 0) any = 1;
    int nz = __syncthreads_or(any);
    if (threadIdx.x == 0) g_is64 = nz ? 0 : 1;
}

// -------- CSR construction (4 edges per thread) --------
__global__ void hist4(const void* __restrict__ ei) {
    int i4 = blockIdx.x * blockDim.x + threadIdx.x;
    int i0 = i4 * 4;
    if (i0 >= ET) return;
    int d[4];
    if (i0 >= EE) {                        // EE %4==0 -> group never straddles
        d[0] = i0 - EE; d[1] = d[0] + 1; d[2] = d[0] + 2; d[3] = d[0] + 3;
    } else if (g_is64) {
        longlong2 a = ((const longlong2*)((const long long*)ei + EE))[i4 * 2];
        longlong2 c = ((const longlong2*)((const long long*)ei + EE))[i4 * 2 + 1];
        d[0] = (int)a.x; d[1] = (int)a.y; d[2] = (int)c.x; d[3] = (int)c.y;
    } else {
        int4 a = ((const int4*)((const int*)ei + EE))[i4];
        d[0] = a.x; d[1] = a.y; d[2] = a.z; d[3] = a.w;
    }
#pragma unroll
    for (int k = 0; k < 4; k++) atomicAdd(&g_cnt[d[k]], 1);
}

// -------- single-kernel scan: decoupled lookback (49 blocks, all resident) --
__global__ void scan_lookback() {
    __shared__ int sh[SCAN_B];
    __shared__ int sh_run;
    int t   = threadIdx.x;
    int bid = blockIdx.x;
    int i   = bid * SCAN_B + t;
    int v   = (i < NN) ? g_cnt[i] : 0;
    sh[t] = v;
    __syncthreads();
#pragma unroll
    for (int o = 1; o < SCAN_B; o <<= 1) {
        int add = (t >= o) ? sh[t - o] : 0;
        __syncthreads();
        sh[t] += add;
        __syncthreads();
    }
    int agg = sh[SCAN_B - 1];

    if (t == 0) {
        if (bid > 0)
            atomicExch(&g_pub[bid], (agg << 2) | 1);   // publish aggregate
        int run = 0;
        for (int j = bid - 1; j >= 0; ) {
            int p;
            do { p = atomicAdd(&g_pub[j], 0); } while ((p & 3) == 0);
            run += (p >> 2);
            if ((p & 3) == 2) break;
            j--;
        }
        atomicExch(&g_pub[bid], ((run + agg) << 2) | 2);  // publish inclusive
        sh_run = run;
    }
    __syncthreads();
    int excl = sh[t] - v + sh_run;
    if (i < NN) { g_off[i] = excl; g_cur[i] = excl; }
    if (i == 0) g_off[NN] = ET;      // total is a compile-time constant
}

__global__ void scatter4(const void* __restrict__ ei) {
    int i4 = blockIdx.x * blockDim.x + threadIdx.x;
    int i0 = i4 * 4;
    if (i0 >= ET) return;
    int s[4], d[4];
    if (i0 >= EE) {
        s[0] = d[0] = i0 - EE;
#pragma unroll
        for (int k = 1; k < 4; k++) { s[k] = d[k] = s[0] + k; }
    } else if (g_is64) {
        longlong2 sa = ((const longlong2*)ei)[i4 * 2];
        longlong2 sb = ((const longlong2*)ei)[i4 * 2 + 1];
        longlong2 da = ((const longlong2*)((const long long*)ei + EE))[i4 * 2];
        longlong2 db = ((const longlong2*)((const long long*)ei + EE))[i4 * 2 + 1];
        s[0] = (int)sa.x; s[1] = (int)sa.y; s[2] = (int)sb.x; s[3] = (int)sb.y;
        d[0] = (int)da.x; d[1] = (int)da.y; d[2] = (int)db.x; d[3] = (int)db.y;
    } else {
        int4 sa = ((const int4*)ei)[i4];
        int4 da = ((const int4*)((const int*)ei + EE))[i4];
        s[0] = sa.x; s[1] = sa.y; s[2] = sa.z; s[3] = sa.w;
        d[0] = da.x; d[1] = da.y; d[2] = da.z; d[3] = da.w;
    }
#pragma unroll
    for (int k = 0; k < 4; k++) {
        int p = atomicAdd(&g_cur[d[k]], 1);
        g_csr[p] = s[k];
    }
}

// -------- GEMM + attention-logit fusion (32 nodes/block, 512 threads) ------
template <int FIN, bool USE_X2>
__global__ void gemm_alpha(const float* __restrict__ xin,
                           const float* __restrict__ W,
                           const float* __restrict__ a_src,
                           const float* __restrict__ a_dst) {
    __shared__ float sW[FIN * 64];
    __shared__ float sX[32 * FIN];

    const float* x = USE_X2 ? g_x2 : xin;
    int t = threadIdx.x;
    int node0 = blockIdx.x * 32;

    for (int i = t; i < FIN * 16; i += 512)
        ((float4*)sW)[i] = ((const float4*)W)[i];
    for (int i = t; i < 8 * FIN; i += 512) {
        int n = node0 + i / (FIN / 4);
        ((float4*)sX)[i] = (n < NN) ? ((const float4*)x)[(long)n * (FIN / 4) + (i % (FIN / 4))]
                                    : make_float4(0.f, 0.f, 0.f, 0.f);
    }
    __syncthreads();

    int node = t >> 4;
    int f4   = t & 15;
    float4 acc = make_float4(0.f, 0.f, 0.f, 0.f);

#pragma unroll 4
    for (int k = 0; k < FIN; k += 4) {
        float4 xv = *(const float4*)&sX[node * FIN + k];
#pragma unroll
        for (int i = 0; i < 4; i++) {
            float xk = (i == 0) ? xv.x : (i == 1) ? xv.y : (i == 2) ? xv.z : xv.w;
            float4 wv = *(const float4*)&sW[(k + i) * 64 + f4 * 4];
            acc.x = fmaf(xk, wv.x, acc.x);
            acc.y = fmaf(xk, wv.y, acc.y);
            acc.z = fmaf(xk, wv.z, acc.z);
            acc.w = fmaf(xk, wv.w, acc.w);
        }
    }

    int n = node0 + node;
    if (n < NN)
        *(float4*)&g_h[(long)n * 64 + f4 * 4] = acc;

    float4 as4 = ((const float4*)a_src)[f4];
    float4 ad4 = ((const float4*)a_dst)[f4];
    float s1 = acc.x * as4.x + acc.y * as4.y + acc.z * as4.z + acc.w * as4.w;
    float s2 = acc.x * ad4.x + acc.y * ad4.y + acc.z * ad4.z + acc.w * ad4.w;
#pragma unroll
    for (int o = 8; o > 0; o >>= 1) {
        s1 += __shfl_down_sync(FULLMASK, s1, o, 16);
        s2 += __shfl_down_sync(FULLMASK, s2, o, 16);
    }
    if (f4 == 0 && n < NN) {
        g_as[n] = s1;
        g_ad[n] = s2;
    }
}

// -------- fused softmax + aggregation; 2 edges per warp instruction --------
// warp per node; lanes 0-15 process even edges (float4), lanes 16-31 odd.
template <bool LAYER2>
__global__ void gat_node(const float* __restrict__ b, float* __restrict__ out) {
    __shared__ int   sS[8][DEGCAP];
    __shared__ float sV[8][DEGCAP];

    int w    = threadIdx.x >> 5;
    int lane = threadIdx.x & 31;
    int half = lane >> 4;        // 0: even edge of pair, 1: odd
    int fl   = lane & 15;        // feature quad index
    int n    = blockIdx.x * 8 + w;
    if (n >= NN) return;

    int off = g_off[n];
    int end = g_off[n + 1];
    int deg = end - off;
    float ad_n = g_ad[n];
    float4 acc = make_float4(0.f, 0.f, 0.f, 0.f);
    float inv;

    if (deg <= DEGCAP) {
        // pass 1a: logits into smem, track max
        float m = -1e30f;
        for (int j = lane; j < deg; j += 32) {
            int s = g_csr[off + j];
            float v = g_as[s] + ad_n;
            v = (v > 0.0f) ? v : NEG_SLOPE * v;
            sS[w][j] = s;
            sV[w][j] = v;
            m = fmaxf(m, v);
        }
#pragma unroll
        for (int o = 16; o > 0; o >>= 1)
            m = fmaxf(m, __shfl_xor_sync(FULLMASK, m, o));

        // pass 1b: exp in place, sum
        float ssum = 0.0f;
        for (int j = lane; j < deg; j += 32) {
            float wt = __expf(sV[w][j] - m);
            sV[w][j] = wt;
            ssum += wt;
        }
#pragma unroll
        for (int o = 16; o > 0; o >>= 1)
            ssum += __shfl_xor_sync(FULLMASK, ssum, o);
        inv = 1.0f / (ssum + 1e-16f);
        __syncwarp();

        // pass 2: 2 edges per step; each half-warp loads a full 256B row
        int j = 0;
        for (; j + 8 <= deg; j += 8) {
#pragma unroll
            for (int u = 0; u < 4; u++) {
                int   s  = sS[w][j + 2 * u + half];
                float wt = sV[w][j + 2 * u + half];
                float4 hv = *(const float4*)(g_h + (long)s * 64 + fl * 4);
                acc.x = fmaf(wt, hv.x, acc.x);
                acc.y = fmaf(wt, hv.y, acc.y);
                acc.z = fmaf(wt, hv.z, acc.z);
                acc.w = fmaf(wt, hv.w, acc.w);
            }
        }
        for (; j + 1 < deg; j += 2) {
            int   s  = sS[w][j + half];
            float wt = sV[w][j + half];
            float4 hv = *(const float4*)(g_h + (long)s * 64 + fl * 4);
            acc.x = fmaf(wt, hv.x, acc.x);
            acc.y = fmaf(wt, hv.y, acc.y);
            acc.z = fmaf(wt, hv.z, acc.z);
            acc.w = fmaf(wt, hv.w, acc.w);
        }
        if (j < deg && half == 0) {          // odd tail edge
            int   s  = sS[w][j];
            float wt = sV[w][j];
            float4 hv = *(const float4*)(g_h + (long)s * 64 + fl * 4);
            acc.x = fmaf(wt, hv.x, acc.x);
            acc.y = fmaf(wt, hv.y, acc.y);
            acc.z = fmaf(wt, hv.z, acc.z);
            acc.w = fmaf(wt, hv.w, acc.w);
        }
    } else {
        // fallback (degree > DEGCAP): online softmax, recompute weights
        float m = -1e30f, ssum = 0.0f;
        for (int e = off + lane; e < end; e += 32) {
            int s = g_csr[e];
            float v = g_as[s] + ad_n;
            v = (v > 0.0f) ? v : NEG_SLOPE * v;
            if (v <= m) {
                ssum += __expf(v - m);
            } else {
                ssum = ssum * __expf(m - v) + 1.0f;
                m = v;
            }
        }
#pragma unroll
        for (int o = 16; o > 0; o >>= 1) {
            float m2 = __shfl_down_sync(FULLMASK, m, o);
            float s2 = __shfl_down_sync(FULLMASK, ssum, o);
            float M = fmaxf(m, m2);
            ssum = ssum * __expf(m - M) + s2 * __expf(m2 - M);
            m = M;
        }
        m    = __shfl_sync(FULLMASK, m, 0);
        ssum = __shfl_sync(FULLMASK, ssum, 0);
        inv  = 1.0f / (ssum + 1e-16f);

        int e = off;
        for (; e + 1 < end; e += 2) {
            int s = g_csr[e + half];
            float v = g_as[s] + ad_n;
            v = (v > 0.0f) ? v : NEG_SLOPE * v;
            float wt = __expf(v - m);
            float4 hv = *(const float4*)(g_h + (long)s * 64 + fl * 4);
            acc.x = fmaf(wt, hv.x, acc.x);
            acc.y = fmaf(wt, hv.y, acc.y);
            acc.z = fmaf(wt, hv.z, acc.z);
            acc.w = fmaf(wt, hv.w, acc.w);
        }
        if (e < end && half == 0) {
            int s = g_csr[e];
            float v = g_as[s] + ad_n;
            v = (v > 0.0f) ? v : NEG_SLOPE * v;
            float wt = __expf(v - m);
            float4 hv = *(const float4*)(g_h + (long)s * 64 + fl * 4);
            acc.x = fmaf(wt, hv.x, acc.x);
            acc.y = fmaf(wt, hv.y, acc.y);
            acc.z = fmaf(wt, hv.z, acc.z);
            acc.w = fmaf(wt, hv.w, acc.w);
        }
    }

    // combine the two edge-halves (lane <-> lane^16 hold same features)
    acc.x += __shfl_xor_sync(FULLMASK, acc.x, 16);
    acc.y += __shfl_xor_sync(FULLMASK, acc.y, 16);
    acc.z += __shfl_xor_sync(FULLMASK, acc.z, 16);
    acc.w += __shfl_xor_sync(FULLMASK, acc.w, 16);

    if (half == 0) {
        float4 bv = ((const float4*)b)[fl];
        float4 o4;
        o4.x = acc.x * inv + bv.x;
        o4.y = acc.y * inv + bv.y;
        o4.z = acc.z * inv + bv.z;
        o4.w = acc.w * inv + bv.w;
        if (!LAYER2) {
            o4.x = fmaxf(o4.x, 0.0f); o4.y = fmaxf(o4.y, 0.0f);
            o4.z = fmaxf(o4.z, 0.0f); o4.w = fmaxf(o4.w, 0.0f);
            *(float4*)&g_x2[(long)n * 64 + fl * 4] = o4;
        } else {
            *(float4*)&out[(long)n * 64 + fl * 4] = o4;
        }
    }
}

extern "C" void kernel_launch(void* const* d_in, const int* in_sizes, int n_in,
                              void* d_out, int out_size) {
    const float* x   = (const float*)d_in[0];
    const void*  ei  = d_in[1];
    const float* W1  = (const float*)d_in[2];
    const float* a1s = (const float*)d_in[3];
    const float* a1d = (const float*)d_in[4];
    const float* b1  = (const float*)d_in[5];
    const float* W2  = (const float*)d_in[6];
    const float* a2s = (const float*)d_in[7];
    const float* a2d = (const float*)d_in[8];
    const float* b2  = (const float*)d_in[9];
    float* out = (float*)d_out;

    const int TB = 256;
    const int gNodes = (NN + 31) / 32;
    const int gEdge4 = (ET / 4 + TB - 1) / TB;
    const int gGat   = (NN + 7) / 8;

    void *cntp, *pubp;
    cudaGetSymbolAddress(&cntp, g_cnt);
    cudaGetSymbolAddress(&pubp, g_pub);

    // fork: layer-1 GEMM concurrent with CSR build
    cudaEventRecord(g_evF, 0);
    cudaStreamWaitEvent(g_s2, g_evF, 0);
    gemm_alpha<128, false><<<gNodes, 512, 0, g_s2>>>(x, W1, a1s, a1d);

    detect_dtype<<<1, 256>>>((const int*)ei);
    cudaMemsetAsync(cntp, 0, NN * sizeof(int), 0);
    cudaMemsetAsync(pubp, 0, NBLK * sizeof(int), 0);
    hist4<<<gEdge4, TB>>>(ei);
    scan_lookback<<<NBLK, SCAN_B>>>();
    scatter4<<<gEdge4, TB>>>(ei);

    cudaEventRecord(g_evJ, g_s2);
    cudaStreamWaitEvent(0, g_evJ, 0);

    // ---- layer 1 ----
    gat_node<false><<<gGat, TB>>>(b1, nullptr);

    // ---- layer 2 ----
    gemm_alpha<64, true><<<gNodes, 512>>>(nullptr, W2, a2s, a2d);
    gat_node<true><<<gGat, TB>>>(b2, out);
}

// round 12
// speedup vs baseline: 1.0449x; 1.0449x over previous
#include <cuda_runtime.h>

#define NN 50000
#define EE 800000
#define ET (EE + NN)
#define NEG_SLOPE 0.2f
#define FULLMASK 0xFFFFFFFFu
#define SCAN_B 1024
#define NBLK ((NN + SCAN_B - 1) / SCAN_B)   // 49
#define DEGCAP 128

// -------- scratch (static __device__ — no allocations allowed) --------
__device__ float g_h[NN * 64];      // layer-1 h
__device__ float g_h2[NN * 64];     // layer-2 h (written by fused epilogue)
__device__ float g_as[NN];          // layer-1 alpha_src
__device__ float g_ad[NN];          // layer-1 alpha_dst
__device__ float g_as2[NN];         // layer-2 alpha_src (separate: race-free)
__device__ float g_ad2[NN];         // layer-2 alpha_dst
__device__ int   g_cnt[NN];
__device__ int   g_off[NN + 1];
__device__ int   g_cur[NN];
__device__ int   g_csr[ET];
__device__ int   g_blksum[NBLK];
__device__ int   g_is64;

// host-side stream/event for graph fork
static cudaStream_t g_s2;
static cudaEvent_t  g_evF, g_evJ;
static struct StreamInit {
    StreamInit() {
        cudaStreamCreateWithFlags(&g_s2, cudaStreamNonBlocking);
        cudaEventCreateWithFlags(&g_evF, cudaEventDisableTiming);
        cudaEventCreateWithFlags(&g_evJ, cudaEventDisableTiming);
    }
} g_stream_init;

// -------- dtype detection --------
__global__ void detect_dtype(const int* __restrict__ ei32) {
    int any = 0;
    for (int i = threadIdx.x; i < 1024; i += 256)
        if (ei32[2 * i + 1] != 0) any = 1;
    int nz = __syncthreads_or(any);
    if (threadIdx.x == 0) g_is64 = nz ? 0 : 1;
}

// -------- CSR construction (4 edges per thread) --------
__global__ void hist4(const void* __restrict__ ei) {
    int i4 = blockIdx.x * blockDim.x + threadIdx.x;
    int i0 = i4 * 4;
    if (i0 >= ET) return;
    int d[4];
    if (i0 >= EE) {                        // EE%4==0 -> no straddle
        d[0] = i0 - EE; d[1] = d[0] + 1; d[2] = d[0] + 2; d[3] = d[0] + 3;
    } else if (g_is64) {
        longlong2 a = ((const longlong2*)((const long long*)ei + EE))[i4 * 2];
        longlong2 c = ((const longlong2*)((const long long*)ei + EE))[i4 * 2 + 1];
        d[0] = (int)a.x; d[1] = (int)a.y; d[2] = (int)c.x; d[3] = (int)c.y;
    } else {
        int4 a = ((const int4*)((const int*)ei + EE))[i4];
        d[0] = a.x; d[1] = a.y; d[2] = a.z; d[3] = a.w;
    }
#pragma unroll
    for (int k = 0; k < 4; k++) atomicAdd(&g_cnt[d[k]], 1);
}

// -------- two-kernel scan --------
__global__ void scan_block() {
    __shared__ int sh[SCAN_B];
    int t = threadIdx.x;
    int i = blockIdx.x * SCAN_B + t;
    int v = (i < NN) ? g_cnt[i] : 0;
    sh[t] = v;
    __syncthreads();
#pragma unroll
    for (int o = 1; o < SCAN_B; o <<= 1) {
        int add = (t >= o) ? sh[t - o] : 0;
        __syncthreads();
        sh[t] += add;
        __syncthreads();
    }
    if (i < NN) g_off[i] = sh[t] - v;          // local exclusive
    if (t == SCAN_B - 1) g_blksum[blockIdx.x] = sh[t];
}

// merged tops+add: each block redundantly scans the 49 block totals
__global__ void scan_add2() {
    __shared__ int spre[NBLK];
    int t = threadIdx.x;
    if (t == 0) {
        int run = 0;
        for (int j = 0; j < NBLK; j++) { spre[j] = run; run += g_blksum[j]; }
    }
    __syncthreads();
    int i = blockIdx.x * blockDim.x + t;
    if (i < NN) {
        int v = g_off[i] + spre[i >> 10];       // SCAN_B = 1024
        g_off[i] = v;
        g_cur[i] = v;
    }
    if (i == 0) g_off[NN] = ET;
}

__global__ void scatter4(const void* __restrict__ ei) {
    int i4 = blockIdx.x * blockDim.x + threadIdx.x;
    int i0 = i4 * 4;
    if (i0 >= ET) return;
    int s[4], d[4];
    if (i0 >= EE) {
        s[0] = d[0] = i0 - EE;
#pragma unroll
        for (int k = 1; k < 4; k++) { s[k] = d[k] = s[0] + k; }
    } else if (g_is64) {
        longlong2 sa = ((const longlong2*)ei)[i4 * 2];
        longlong2 sb = ((const longlong2*)ei)[i4 * 2 + 1];
        longlong2 da = ((const longlong2*)((const long long*)ei + EE))[i4 * 2];
        longlong2 db = ((const longlong2*)((const long long*)ei + EE))[i4 * 2 + 1];
        s[0] = (int)sa.x; s[1] = (int)sa.y; s[2] = (int)sb.x; s[3] = (int)sb.y;
        d[0] = (int)da.x; d[1] = (int)da.y; d[2] = (int)db.x; d[3] = (int)db.y;
    } else {
        int4 sa = ((const int4*)ei)[i4];
        int4 da = ((const int4*)((const int*)ei + EE))[i4];
        s[0] = sa.x; s[1] = sa.y; s[2] = sa.z; s[3] = sa.w;
        d[0] = da.x; d[1] = da.y; d[2] = da.z; d[3] = da.w;
    }
#pragma unroll
    for (int k = 0; k < 4; k++) {
        int p = atomicAdd(&g_cur[d[k]], 1);
        g_csr[p] = s[k];
    }
}

// -------- layer-1 GEMM + attention logits (32 nodes/block, 512 threads) ----
__global__ void gemm_alpha1(const float* __restrict__ x,
                            const float* __restrict__ W,
                            const float* __restrict__ a_src,
                            const float* __restrict__ a_dst) {
    const int FIN = 128;
    __shared__ float sW[FIN * 64];
    __shared__ float sX[32 * FIN];

    int t = threadIdx.x;
    int node0 = blockIdx.x * 32;

    for (int i = t; i < FIN * 16; i += 512)
        ((float4*)sW)[i] = ((const float4*)W)[i];
    for (int i = t; i < 8 * FIN; i += 512) {
        int n = node0 + i / (FIN / 4);
        ((float4*)sX)[i] = (n < NN) ? ((const float4*)x)[(long)n * (FIN / 4) + (i % (FIN / 4))]
                                    : make_float4(0.f, 0.f, 0.f, 0.f);
    }
    __syncthreads();

    int node = t >> 4;
    int f4   = t & 15;
    float4 acc = make_float4(0.f, 0.f, 0.f, 0.f);

#pragma unroll 4
    for (int k = 0; k < FIN; k += 4) {
        float4 xv = *(const float4*)&sX[node * FIN + k];
#pragma unroll
        for (int i = 0; i < 4; i++) {
            float xk = (i == 0) ? xv.x : (i == 1) ? xv.y : (i == 2) ? xv.z : xv.w;
            float4 wv = *(const float4*)&sW[(k + i) * 64 + f4 * 4];
            acc.x = fmaf(xk, wv.x, acc.x);
            acc.y = fmaf(xk, wv.y, acc.y);
            acc.z = fmaf(xk, wv.z, acc.z);
            acc.w = fmaf(xk, wv.w, acc.w);
        }
    }

    int n = node0 + node;
    if (n < NN)
        *(float4*)&g_h[(long)n * 64 + f4 * 4] = acc;

    float4 as4 = ((const float4*)a_src)[f4];
    float4 ad4 = ((const float4*)a_dst)[f4];
    float s1 = acc.x * as4.x + acc.y * as4.y + acc.z * as4.z + acc.w * as4.w;
    float s2 = acc.x * ad4.x + acc.y * ad4.y + acc.z * ad4.z + acc.w * ad4.w;
#pragma unroll
    for (int o = 8; o > 0; o >>= 1) {
        s1 += __shfl_down_sync(FULLMASK, s1, o, 16);
        s2 += __shfl_down_sync(FULLMASK, s2, o, 16);
    }
    if (f4 == 0 && n < NN) {
        g_as[n] = s1;
        g_ad[n] = s2;
    }
}

// -------- shared per-node softmax+gather core (alpha arrays as params) -----
__device__ __forceinline__ void gat_core(const float* __restrict__ hsrc,
                                         const float* __restrict__ as,
                                         const float* __restrict__ ad,
                                         int n, int w, int lane,
                                         int (&sS)[8][DEGCAP],
                                         float (&sV)[8][DEGCAP],
                                         float& accx, float& accy, float& inv) {
    int off = g_off[n];
    int end = g_off[n + 1];
    int deg = end - off;
    float ad_n = ad[n];
    accx = 0.0f; accy = 0.0f;

    if (deg <= DEGCAP) {
        float m = -1e30f;
        for (int j = lane; j < deg; j += 32) {
            int s = g_csr[off + j];
            float v = as[s] + ad_n;
            v = (v > 0.0f) ? v : NEG_SLOPE * v;
            sS[w][j] = s;
            sV[w][j] = v;
            m = fmaxf(m, v);
        }
#pragma unroll
        for (int o = 16; o > 0; o >>= 1)
            m = fmaxf(m, __shfl_xor_sync(FULLMASK, m, o));

        float ssum = 0.0f;
        for (int j = lane; j < deg; j += 32) {
            float wt = __expf(sV[w][j] - m);
            sV[w][j] = wt;
            ssum += wt;
        }
#pragma unroll
        for (int o = 16; o > 0; o >>= 1)
            ssum += __shfl_xor_sync(FULLMASK, ssum, o);
        inv = 1.0f / (ssum + 1e-16f);
        __syncwarp();

        int j = 0;
        for (; j + 4 <= deg; j += 4) {
            int   s0 = sS[w][j],     s1 = sS[w][j + 1];
            int   s2 = sS[w][j + 2], s3 = sS[w][j + 3];
            float w0 = sV[w][j],     w1 = sV[w][j + 1];
            float w2 = sV[w][j + 2], w3 = sV[w][j + 3];
            float2 h0 = *(const float2*)(hsrc + (long)s0 * 64 + lane * 2);
            float2 h1 = *(const float2*)(hsrc + (long)s1 * 64 + lane * 2);
            float2 h2 = *(const float2*)(hsrc + (long)s2 * 64 + lane * 2);
            float2 h3 = *(const float2*)(hsrc + (long)s3 * 64 + lane * 2);
            accx = fmaf(w0, h0.x, accx); accy = fmaf(w0, h0.y, accy);
            accx = fmaf(w1, h1.x, accx); accy = fmaf(w1, h1.y, accy);
            accx = fmaf(w2, h2.x, accx); accy = fmaf(w2, h2.y, accy);
            accx = fmaf(w3, h3.x, accx); accy = fmaf(w3, h3.y, accy);
        }
        for (; j < deg; j++) {
            int   s0 = sS[w][j];
            float w0 = sV[w][j];
            float2 h0 = *(const float2*)(hsrc + (long)s0 * 64 + lane * 2);
            accx = fmaf(w0, h0.x, accx);
            accy = fmaf(w0, h0.y, accy);
        }
    } else {
        // fallback: online softmax, recompute weights
        float m = -1e30f, ssum = 0.0f;
        for (int e = off + lane; e < end; e += 32) {
            int s = g_csr[e];
            float v = as[s] + ad_n;
            v = (v > 0.0f) ? v : NEG_SLOPE * v;
            if (v <= m) {
                ssum += __expf(v - m);
            } else {
                ssum = ssum * __expf(m - v) + 1.0f;
                m = v;
            }
        }
#pragma unroll
        for (int o = 16; o > 0; o >>= 1) {
            float m2 = __shfl_down_sync(FULLMASK, m, o);
            float s2 = __shfl_down_sync(FULLMASK, ssum, o);
            float M = fmaxf(m, m2);
            ssum = ssum * __expf(m - M) + s2 * __expf(m2 - M);
            m = M;
        }
        m    = __shfl_sync(FULLMASK, m, 0);
        ssum = __shfl_sync(FULLMASK, ssum, 0);
        inv  = 1.0f / (ssum + 1e-16f);

        for (int e = off; e < end; e++) {
            int s0 = g_csr[e];
            float v0 = as[s0] + ad_n;
            v0 = (v0 > 0.0f) ? v0 : NEG_SLOPE * v0;
            float w0 = __expf(v0 - m);
            float2 h0 = *(const float2*)(hsrc + (long)s0 * 64 + lane * 2);
            accx = fmaf(w0, h0.x, accx);
            accy = fmaf(w0, h0.y, accy);
        }
    }
}

// -------- layer-1 aggregation FUSED with layer-2 GEMM + alphas -------------
// 8 warps = 8 nodes per block (NN % 8 == 0 -> no early exit, barrier legal)
__global__ void gat_fused(const float* __restrict__ b1,
                          const float* __restrict__ W2,
                          const float* __restrict__ a2s,
                          const float* __restrict__ a2d) {
    __shared__ int   sS[8][DEGCAP];
    __shared__ float sV[8][DEGCAP];
    __shared__ float sW2[64 * 64];
    __shared__ float sX2[8][64];

    int t = threadIdx.x;
    for (int i = t; i < 64 * 16; i += 256)     // 16 KB W2, once per block
        ((float4*)sW2)[i] = ((const float4*)W2)[i];
    __syncthreads();

    int w = t >> 5, lane = t & 31;
    int n = blockIdx.x * 8 + w;

    float accx, accy, inv;
    gat_core(g_h, g_as, g_ad, n, w, lane, sS, sV, accx, accy, inv);

    // x2 row (relu(agg + b1)) staged per warp
    float x2a = fmaxf(accx * inv + b1[lane * 2],     0.0f);
    float x2b = fmaxf(accy * inv + b1[lane * 2 + 1], 0.0f);
    sX2[w][lane * 2]     = x2a;
    sX2[w][lane * 2 + 1] = x2b;
    __syncwarp();

    // h2 = x2 @ W2 : each lane computes 2 output features
    float h2a = 0.0f, h2b = 0.0f;
#pragma unroll 8
    for (int k = 0; k < 64; k++) {
        float xk = sX2[w][k];
        float2 wv = *(const float2*)&sW2[k * 64 + lane * 2];
        h2a = fmaf(xk, wv.x, h2a);
        h2b = fmaf(xk, wv.y, h2b);
    }
    *(float2*)&g_h2[(long)n * 64 + lane * 2] = make_float2(h2a, h2b);

    // layer-2 attention partials -> SEPARATE arrays (no race with layer-1 reads)
    float2 asv = *(const float2*)&a2s[lane * 2];
    float2 adv = *(const float2*)&a2d[lane * 2];
    float s1 = h2a * asv.x + h2b * asv.y;
    float s2 = h2a * adv.x + h2b * adv.y;
#pragma unroll
    for (int o = 16; o > 0; o >>= 1) {
        s1 += __shfl_down_sync(FULLMASK, s1, o);
        s2 += __shfl_down_sync(FULLMASK, s2, o);
    }
    if (lane == 0) {
        g_as2[n] = s1;
        g_ad2[n] = s2;
    }
}

// -------- layer-2 aggregation -> output ------------------------------------
__global__ void gat_out(const float* __restrict__ b2, float* __restrict__ out) {
    __shared__ int   sS[8][DEGCAP];
    __shared__ float sV[8][DEGCAP];

    int t = threadIdx.x;
    int w = t >> 5, lane = t & 31;
    int n = blockIdx.x * 8 + w;

    float accx, accy, inv;
    gat_core(g_h2, g_as2, g_ad2, n, w, lane, sS, sV, accx, accy, inv);

    long idx = (long)n * 64 + lane * 2;
    out[idx]     = accx * inv + b2[lane * 2];
    out[idx + 1] = accy * inv + b2[lane * 2 + 1];
}

extern "C" void kernel_launch(void* const* d_in, const int* in_sizes, int n_in,
                              void* d_out, int out_size) {
    const float* x   = (const float*)d_in[0];
    const void*  ei  = d_in[1];
    const float* W1  = (const float*)d_in[2];
    const float* a1s = (const float*)d_in[3];
    const float* a1d = (const float*)d_in[4];
    const float* b1  = (const float*)d_in[5];
    const float* W2  = (const float*)d_in[6];
    const float* a2s = (const float*)d_in[7];
    const float* a2d = (const float*)d_in[8];
    const float* b2  = (const float*)d_in[9];
    float* out = (float*)d_out;

    const int TB = 256;
    const int gNodes = (NN + 31) / 32;
    const int gEdge4 = (ET / 4 + TB - 1) / TB;
    const int gN     = (NN + TB - 1) / TB;
    const int gGat   = NN / 8;                 // 6250, exact

    void* cntp;
    cudaGetSymbolAddress(&cntp, g_cnt);

    // fork: layer-1 GEMM concurrent with CSR build
    cudaEventRecord(g_evF, 0);
    cudaStreamWaitEvent(g_s2, g_evF, 0);
    gemm_alpha1<<<gNodes, 512, 0, g_s2>>>(x, W1, a1s, a1d);

    detect_dtype<<<1, 256>>>((const int*)ei);
    cudaMemsetAsync(cntp, 0, NN * sizeof(int), 0);
    hist4<<<gEdge4, TB>>>(ei);
    scan_block<<<NBLK, SCAN_B>>>();
    scan_add2<<<gN, TB>>>();
    scatter4<<<gEdge4, TB>>>(ei);

    cudaEventRecord(g_evJ, g_s2);
    cudaStreamWaitEvent(0, g_evJ, 0);

    // layer 1 aggregation + fused layer-2 GEMM/alphas
    gat_fused<<<gGat, TB>>>(b1, W2, a2s, a2d);

    // layer 2 aggregation -> output
    gat_out<<<gGat, TB>>>(b2, out);
}